// round 4
// baseline (speedup 1.0000x reference)
#include <cuda_runtime.h>

// Problem constants (hard-coded in reference)
#define S7      7
#define CELLS   49
#define BTOT    16384
#define NCELLS  (BTOT * CELLS)          // 802816
#define IMGF    448.0f
#define CELLF   64.0f
#define NBLOCKS (NCELLS / 256)          // 3136 exactly

// Scratch for block partial sums (allocation-free: __device__ global)
__device__ float g_partials[NBLOCKS];

__device__ __forceinline__ void decode_box(float p0, float p1, float p2, float p3,
                                           float gx, float gy,
                                           float& x1, float& y1, float& x2, float& y2) {
    float cx = fmaf(p0, CELLF, gx);
    float cy = fmaf(p1, CELLF, gy);
    float w  = p2 * IMGF;
    float h  = p3 * IMGF;
    x1 = fminf(fmaxf(cx - 0.5f * w, 0.0f), IMGF);
    y1 = fminf(fmaxf(cy - 0.5f * h, 0.0f), IMGF);
    x2 = fminf(fmaxf(cx + 0.5f * w, 0.0f), IMGF);
    y2 = fminf(fmaxf(cy + 0.5f * h, 0.0f), IMGF);
}

__device__ __forceinline__ float iou_fn(float ax1, float ay1, float ax2, float ay2,
                                        float bx1, float by1, float bx2, float by2) {
    float l  = fmaxf(ax1, bx1);
    float r  = fminf(ax2, bx2);
    float t  = fmaxf(ay1, by1);
    float bo = fminf(ay2, by2);
    bool  m  = (l < r) && (t < bo);
    float inter = (r - l) * (bo - t);
    float uni   = (ax2 - ax1) * (ay2 - ay1) + (bx2 - bx1) * (by2 - by1);
    float denom = uni - inter;
    return m ? (inter / denom) : 0.0f;
}

__global__ __launch_bounds__(256)
void yolo_loss_main(const float* __restrict__ inp,   // [B,30,7,7]
                    const float* __restrict__ tgt)   // [B,7,7,30]
{
    int n = blockIdx.x * 256 + threadIdx.x;          // global cell id, always < NCELLS

    int b    = n / CELLS;
    int cell = n - b * CELLS;
    int row  = cell / S7;
    int col  = cell - row * S7;
    float gx = (float)col * CELLF;
    float gy = (float)row * CELLF;

    // input: element (b, k, cell) at b*1470 + k*49 + cell  -> coalesced across warp
    const float* xin = inp + (long long)b * 1470 + cell;
    const float* tp  = tgt + (long long)n * 30;

    float x[10], t[10];
#pragma unroll
    for (int k = 0; k < 10; k++) x[k] = __ldg(xin + k * CELLS);
#pragma unroll
    for (int k = 0; k < 10; k++) t[k] = __ldg(tp + k);

    // Decode predicted boxes 0 and 1, target boxes 0 and 1
    float px1a, py1a, px2a, py2a, px1b, py1b, px2b, py2b;
    float tx1a, ty1a, tx2a, ty2a, tx1b, ty1b, tx2b, ty2b;
    decode_box(x[0], x[1], x[2], x[3], gx, gy, px1a, py1a, px2a, py2a);
    decode_box(x[5], x[6], x[7], x[8], gx, gy, px1b, py1b, px2b, py2b);
    decode_box(t[0], t[1], t[2], t[3], gx, gy, tx1a, ty1a, tx2a, ty2a);
    decode_box(t[5], t[6], t[7], t[8], gx, gy, tx1b, ty1b, tx2b, ty2b);

    float iou1 = iou_fn(px1a, py1a, px2a, py2a, tx1a, ty1a, tx2a, ty2a);
    float iou2 = iou_fn(px1b, py1b, px2b, py2b, tx1b, ty1b, tx2b, ty2b);

    bool  msk  = iou1 < iou2;                // second box responsible
    float iou  = msk ? iou2 : iou1;
    float s0 = msk ? x[5] : x[0];
    float s1 = msk ? x[6] : x[1];
    float s2 = msk ? x[7] : x[2];
    float s3 = msk ? x[8] : x[3];
    float s4 = msk ? x[9] : x[4];

    bool hasObj = (t[4] == 1.0f);

    float loss;
    if (hasObj) {
        float d0 = s0 - t[0], d1 = s1 - t[1];
        float coord = d0 * d0 + d1 * d1;
        float ds2 = sqrtf(s2) - sqrtf(t[2]);
        float ds3 = sqrtf(s3) - sqrtf(t[3]);
        float size = ds2 * ds2 + ds3 * ds3;
        float dc = s4 - iou;
        float conf = dc * dc;
        float cls = 0.0f;
#pragma unroll
        for (int k = 10; k < 30; k++) {
            float d = __ldg(xin + k * CELLS) - __ldg(tp + k);
            cls = fmaf(d, d, cls);
        }
        loss = 5.0f * coord + 5.0f * size + conf + cls;
    } else {
        loss = 0.5f * (s4 * s4);             // noobj term only
    }

    // Block reduction (fp32; <= 256 terms, magnitudes O(1..10))
    __shared__ float warp_sums[8];
    unsigned fullmask = 0xFFFFFFFFu;
#pragma unroll
    for (int off = 16; off > 0; off >>= 1)
        loss += __shfl_down_sync(fullmask, loss, off);

    int lane = threadIdx.x & 31;
    int wid  = threadIdx.x >> 5;
    if (lane == 0) warp_sums[wid] = loss;
    __syncthreads();
    if (wid == 0) {
        float v = (lane < 8) ? warp_sums[lane] : 0.0f;
#pragma unroll
        for (int off = 4; off > 0; off >>= 1)
            v += __shfl_down_sync(fullmask, v, off);
        if (lane == 0) g_partials[blockIdx.x] = v;
    }
}

// Single-block final reduction of 3136 partials in double (deterministic order
// per-thread, shuffle tree fixed -> bit-stable across replays).
__global__ __launch_bounds__(1024)
void yolo_loss_reduce(float* __restrict__ out)
{
    double s = 0.0;
    for (int i = threadIdx.x; i < NBLOCKS; i += 1024)
        s += (double)g_partials[i];

    __shared__ double warp_sums[32];
    unsigned fullmask = 0xFFFFFFFFu;
#pragma unroll
    for (int off = 16; off > 0; off >>= 1)
        s += __shfl_down_sync(fullmask, s, off);

    int lane = threadIdx.x & 31;
    int wid  = threadIdx.x >> 5;
    if (lane == 0) warp_sums[wid] = s;
    __syncthreads();
    if (wid == 0) {
        double v = (lane < 32) ? warp_sums[lane] : 0.0;
#pragma unroll
        for (int off = 16; off > 0; off >>= 1)
            v += __shfl_down_sync(fullmask, v, off);
        if (lane == 0) out[0] = (float)v;
    }
}

extern "C" void kernel_launch(void* const* d_in, const int* in_sizes, int n_in,
                              void* d_out, int out_size)
{
    const float* inp = (const float*)d_in[0];   // input_ [B,30,7,7] f32
    const float* tgt = (const float*)d_in[1];   // target [B,7,7,30] f32
    float* out = (float*)d_out;

    yolo_loss_main<<<NBLOCKS, 256>>>(inp, tgt);
    yolo_loss_reduce<<<1, 1024>>>(out);
}